// round 16
// baseline (speedup 1.0000x reference)
#include <cuda_runtime.h>
#include <cuda_bf16.h>
#include <math.h>
#include <stdint.h>

#define Nn 50000
#define Ee 800000
#define Gg 64
#define Rr 3
#define SEGS (Rr * Nn)            // 150000 (relation, dst) segments
#define SCAN_BLKS 148             // 148 * 1024 >= SEGS+1
#define NPAD 50048                // 391 * 128 (row padding for guard-free mma loads)

// ---------------- scratch (static device globals; no allocation) ----------------
__device__ __align__(128) unsigned short d_Ahi[(size_t)NPAD * 1024]; // bf16 hi of A [NPAD,K]
__device__ __align__(128) unsigned short d_Alo[(size_t)NPAD * 1024]; // bf16 lo of A
__device__ __align__(128) unsigned short d_Bth[256 * 1024];          // bf16 hi of B^T [NB,K]
__device__ __align__(128) unsigned short d_Btl[256 * 1024];          // bf16 lo of B^T
__device__ __align__(128) float  d_h[(size_t)Nn * 256];    // layer input, post-BN (stride = din)
__device__ __align__(128) float  d_y[(size_t)Nn * 256];    // pre-BN layer output (stride = dout)
__device__ double d_stat[512];
__device__ float  d_scale[256];
__device__ float  d_shift[256];
__device__ float  d_pool[Gg * 256];
__device__ float  d_poolcnt[Gg];
// CSR structures
__device__ int    d_rowptr[SEGS + 1];
__device__ int    d_blk[SCAN_BLKS];
__device__ int    d_cur[SEGS];
__device__ int    d_col[Ee];

// ---------------- helpers ----------------
__device__ __forceinline__ void split_pair(float x, float y, uint32_t& hi, uint32_t& lo) {
    __nv_bfloat16 hx = __float2bfloat16(x);
    __nv_bfloat16 hy = __float2bfloat16(y);
    float rx = x - __bfloat162float(hx);
    float ry = y - __bfloat162float(hy);
    hi = (uint32_t)__bfloat16_as_ushort(hx) | ((uint32_t)__bfloat16_as_ushort(hy) << 16);
    lo = (uint32_t)__bfloat16_as_ushort(__float2bfloat16(rx))
       | ((uint32_t)__bfloat16_as_ushort(__float2bfloat16(ry)) << 16);
}

#define MMA_BF16(c, a, b) \
    asm volatile("mma.sync.aligned.m16n8k16.row.col.f32.bf16.bf16.f32 " \
                 "{%0,%1,%2,%3}, {%4,%5,%6,%7}, {%8,%9}, {%0,%1,%2,%3};" \
                 : "+f"((c)[0]), "+f"((c)[1]), "+f"((c)[2]), "+f"((c)[3]) \
                 : "r"((a)[0]), "r"((a)[1]), "r"((a)[2]), "r"((a)[3]), \
                   "r"((b)[0]), "r"((b)[1]))

// ---------------- CSR build ----------------
__global__ void zero_ptr_k() {
    int i = blockIdx.x * blockDim.x + threadIdx.x;
    if (i <= SEGS) d_rowptr[i] = 0;
}

__global__ void count_k(const int* __restrict__ et, const int* __restrict__ dst) {
    int e = blockIdx.x * blockDim.x + threadIdx.x;
    if (e < Ee) atomicAdd(&d_rowptr[et[e] * Nn + dst[e] + 1], 1);
}

__global__ void scan1_k() {
    __shared__ int sh[256];
    int blk = blockIdx.x, t = threadIdx.x;
    int base = blk * 1024 + t * 4;
    int v[4];
#pragma unroll
    for (int i = 0; i < 4; i++) {
        int idx = base + i;
        v[i] = (idx <= SEGS) ? d_rowptr[idx] : 0;
    }
    v[1] += v[0]; v[2] += v[1]; v[3] += v[2];
    int tsum = v[3];
    sh[t] = tsum;
    __syncthreads();
    for (int off = 1; off < 256; off <<= 1) {
        int x = (t >= off) ? sh[t - off] : 0;
        __syncthreads();
        sh[t] += x;
        __syncthreads();
    }
    int off0 = sh[t] - tsum;
#pragma unroll
    for (int i = 0; i < 4; i++) {
        int idx = base + i;
        if (idx <= SEGS) d_rowptr[idx] = v[i] + off0;
    }
    if (t == 255) d_blk[blk] = sh[255];
}

__global__ void scan2_k() {
    __shared__ int sh[SCAN_BLKS];
    int t = threadIdx.x;
    if (t < SCAN_BLKS) sh[t] = d_blk[t];
    __syncthreads();
    if (t == 0) {
        int acc = 0;
        for (int b = 0; b < SCAN_BLKS; b++) { int x = sh[b]; sh[b] = acc; acc += x; }
    }
    __syncthreads();
    if (t < SCAN_BLKS) d_blk[t] = sh[t];
}

__global__ void scan3_k() {
    int blk = blockIdx.x, t = threadIdx.x;
    int add = d_blk[blk];
    if (add == 0) return;
    int base = blk * 1024 + t * 4;
#pragma unroll
    for (int i = 0; i < 4; i++) {
        int idx = base + i;
        if (idx <= SEGS) d_rowptr[idx] += add;
    }
}

__global__ void cursor_k() {
    int i = blockIdx.x * blockDim.x + threadIdx.x;
    if (i < SEGS) d_cur[i] = d_rowptr[i];
}

__global__ void fillcol_k(const int* __restrict__ src, const int* __restrict__ dst,
                          const int* __restrict__ et) {
    int e = blockIdx.x * blockDim.x + threadIdx.x;
    if (e >= Ee) return;
    int seg = et[e] * Nn + dst[e];
    int pos = atomicAdd(&d_cur[seg], 1);
    d_col[pos] = src[e];
}

// ---------------- misc copies ----------------
__global__ void copy_x_k(const float* __restrict__ x) {
    int i = blockIdx.x * blockDim.x + threadIdx.x;
    if (i < Nn * 128 / 4) ((float4*)d_h)[i] = ((const float4*)x)[i];
}

// A[n, 0:din] = bf16 hi/lo split of d_h[n]
__global__ void fillh_k(int din, int K) {
    int idx = blockIdx.x * blockDim.x + threadIdx.x;
    int din4 = din >> 2;
    if (idx >= Nn * din4) return;
    int n = idx / din4;
    int c = (idx - n * din4) << 2;
    float4 v = *(const float4*)&d_h[(size_t)n * din + c];
    uint32_t h0, l0, h1, l1;
    split_pair(v.x, v.y, h0, l0);
    split_pair(v.z, v.w, h1, l1);
    size_t off = (size_t)n * K + c;
    *(uint2*)&d_Ahi[off] = make_uint2(h0, h1);
    *(uint2*)&d_Alo[off] = make_uint2(l0, l1);
}

// ---------------- gather: warp per (relation,dst) segment ----------------
__global__ void gather_k(int din, int K) {
    int gt = blockIdx.x * blockDim.x + threadIdx.x;
    int seg = gt >> 5, lane = gt & 31;
    if (seg >= SEGS) return;
    int r = seg / Nn;
    int dstn = seg - r * Nn;
    int beg = d_rowptr[seg];
    int end = d_rowptr[seg + 1];
    int len = end - beg;
    int din4 = din >> 2;
    int q0 = lane, q1 = lane + 32;
    bool h0 = q0 < din4, h1 = q1 < din4;

    float4 acc0 = make_float4(0.f, 0.f, 0.f, 0.f);
    float4 acc1 = acc0;
    for (int e = beg; e < end; e++) {
        int s = d_col[e];
        const float4* hp = (const float4*)(d_h + (size_t)s * din);
        if (h0) {
            float4 v = hp[q0];
            acc0.x += v.x; acc0.y += v.y; acc0.z += v.z; acc0.w += v.w;
        }
        if (h1) {
            float4 v = hp[q1];
            acc1.x += v.x; acc1.y += v.y; acc1.z += v.z; acc1.w += v.w;
        }
    }
    float inv = (len > 0) ? (1.0f / (float)len) : 0.0f;
    size_t base = (size_t)dstn * K + din + r * din;
    if (h0) {
        uint32_t ha, la, hb, lb;
        split_pair(acc0.x * inv, acc0.y * inv, ha, la);
        split_pair(acc0.z * inv, acc0.w * inv, hb, lb);
        size_t off = base + (q0 << 2);
        *(uint2*)&d_Ahi[off] = make_uint2(ha, hb);
        *(uint2*)&d_Alo[off] = make_uint2(la, lb);
    }
    if (h1) {
        uint32_t ha, la, hb, lb;
        split_pair(acc1.x * inv, acc1.y * inv, ha, la);
        split_pair(acc1.z * inv, acc1.w * inv, hb, lb);
        size_t off = base + (q1 << 2);
        *(uint2*)&d_Ahi[off] = make_uint2(ha, hb);
        *(uint2*)&d_Alo[off] = make_uint2(la, lb);
    }
}

// ---------------- weight prep: B^T [NB, K] bf16 hi/lo, n-major ----------------
// B(k,n) = (k < din) ? Rw[k,n] : W[(k-din),n];  Bt[n,k] = split(B(k,n)); zero for n>=dout
__global__ void prepB_k(const float* __restrict__ W, const float* __restrict__ Rw,
                        int K, int din, int dout, int NB) {
    int idx = blockIdx.x * blockDim.x + threadIdx.x;
    int K2 = K >> 1;
    if (idx >= NB * K2) return;
    int n = idx / K2;
    int k = (idx - n * K2) << 1;
    float v0 = 0.f, v1 = 0.f;
    if (n < dout) {
        v0 = (k < din) ? Rw[(size_t)k * dout + n] : W[(size_t)(k - din) * dout + n];
        int k1 = k + 1;
        v1 = (k1 < din) ? Rw[(size_t)k1 * dout + n] : W[(size_t)(k1 - din) * dout + n];
    }
    uint32_t hi, lo;
    split_pair(v0, v1, hi, lo);
    size_t off = (size_t)n * K + k;
    *(uint32_t*)&d_Bth[off] = hi;
    *(uint32_t*)&d_Btl[off] = lo;
}

// ---------------- mma.sync bf16 3-pass GEMM ----------------
// Y[N,dout] = A @ B + bias.  Block 128x128, 8 warps (2m x 4n), warp tile 64x32.
__global__ void __launch_bounds__(256) mma_gemm_k(const float* __restrict__ bias,
                                                  int K, int dout) {
    int t = threadIdx.x, warp = t >> 5, lane = t & 31;
    int gid = lane >> 2, tid4 = lane & 3;
    int wm = warp & 1, wn = warp >> 1;           // 2m x 4n
    int mbase = blockIdx.x * 128 + wm * 64;
    int nbase = blockIdx.y * 128 + wn * 32;

    float acc[4][4][4];
#pragma unroll
    for (int i = 0; i < 4; i++)
#pragma unroll
        for (int j = 0; j < 4; j++)
#pragma unroll
            for (int q = 0; q < 4; q++) acc[i][j][q] = 0.f;

    for (int k0 = 0; k0 < K; k0 += 16) {
        uint32_t ah[4][4], al[4][4], bh[4][2], bl[4][2];
#pragma unroll
        for (int mf = 0; mf < 4; mf++) {
            size_t r0 = (size_t)(mbase + mf * 16 + gid) * K + k0 + tid4 * 2;
            size_t r1 = r0 + (size_t)8 * K;
            ah[mf][0] = *(const uint32_t*)&d_Ahi[r0];
            ah[mf][1] = *(const uint32_t*)&d_Ahi[r1];
            ah[mf][2] = *(const uint32_t*)&d_Ahi[r0 + 8];
            ah[mf][3] = *(const uint32_t*)&d_Ahi[r1 + 8];
            al[mf][0] = *(const uint32_t*)&d_Alo[r0];
            al[mf][1] = *(const uint32_t*)&d_Alo[r1];
            al[mf][2] = *(const uint32_t*)&d_Alo[r0 + 8];
            al[mf][3] = *(const uint32_t*)&d_Alo[r1 + 8];
        }
#pragma unroll
        for (int nf = 0; nf < 4; nf++) {
            size_t q0 = (size_t)(nbase + nf * 8 + gid) * K + k0 + tid4 * 2;
            bh[nf][0] = *(const uint32_t*)&d_Bth[q0];
            bh[nf][1] = *(const uint32_t*)&d_Bth[q0 + 8];
            bl[nf][0] = *(const uint32_t*)&d_Btl[q0];
            bl[nf][1] = *(const uint32_t*)&d_Btl[q0 + 8];
        }
#pragma unroll
        for (int mf = 0; mf < 4; mf++)
#pragma unroll
            for (int nf = 0; nf < 4; nf++) {
                MMA_BF16(acc[mf][nf], ah[mf], bh[nf]);
                MMA_BF16(acc[mf][nf], ah[mf], bl[nf]);
                MMA_BF16(acc[mf][nf], al[mf], bh[nf]);
            }
    }

#pragma unroll
    for (int nf = 0; nf < 4; nf++) {
        int col = nbase + nf * 8 + tid4 * 2;
        if (col >= dout) continue;
        float bx = bias[col], by = bias[col + 1];
#pragma unroll
        for (int mf = 0; mf < 4; mf++) {
            int row0 = mbase + mf * 16 + gid;
            int row1 = row0 + 8;
            if (row0 < Nn)
                *(float2*)&d_y[(size_t)row0 * dout + col] =
                    make_float2(acc[mf][nf][0] + bx, acc[mf][nf][1] + by);
            if (row1 < Nn)
                *(float2*)&d_y[(size_t)row1 * dout + col] =
                    make_float2(acc[mf][nf][2] + bx, acc[mf][nf][3] + by);
        }
    }
}

// ---------------- BatchNorm (training mode; proven) ----------------
__global__ void zero_stat_k() {
    int i = threadIdx.x;
    if (i < 512) d_stat[i] = 0.0;
}

__global__ void stats_k(int dout) {
    int c = threadIdx.x;
    int rows = (Nn + gridDim.x - 1) / gridDim.x;
    int r0 = blockIdx.x * rows;
    int r1 = min(Nn, r0 + rows);
    if (c >= dout) return;
    float s = 0.f, q = 0.f;
    for (int r = r0; r < r1; r++) {
        float v = d_y[(size_t)r * dout + c];
        s += v; q += v * v;
    }
    atomicAdd(&d_stat[c], (double)s);
    atomicAdd(&d_stat[256 + c], (double)q);
}

__global__ void prep_bn_k(const float* __restrict__ gamma, const float* __restrict__ beta, int dout) {
    int c = threadIdx.x;
    if (c >= dout) return;
    double mu  = d_stat[c] / (double)Nn;
    double var = d_stat[256 + c] / (double)Nn - mu * mu;
    float rs = rsqrtf(fmaxf((float)var, 0.f) + 1e-5f);
    float sc = rs * gamma[c];
    d_scale[c] = sc;
    d_shift[c] = beta[c] - (float)mu * sc;
}

__global__ void norm_k(int dout) {
    int idx4 = blockIdx.x * blockDim.x + threadIdx.x;
    int tot = (Nn * dout) >> 2;
    if (idx4 >= tot) return;
    int c = (idx4 << 2) % dout;
    float4 y  = ((const float4*)d_y)[idx4];
    float4 sc = *(const float4*)&d_scale[c];
    float4 sh = *(const float4*)&d_shift[c];
    ((float4*)d_h)[idx4] = make_float4(y.x * sc.x + sh.x, y.y * sc.y + sh.y,
                                       y.z * sc.z + sh.z, y.w * sc.w + sh.w);
}

// ---------------- pooling + MLP head (proven) ----------------
__global__ void zero_pool_k() {
    int i = blockIdx.x * blockDim.x + threadIdx.x;
    if (i < Gg * 256) d_pool[i] = 0.f;
    if (i < Gg) d_poolcnt[i] = 0.f;
}

__global__ void pool_k(const int* __restrict__ batch) {
    int gt = blockIdx.x * blockDim.x + threadIdx.x;
    int n = gt >> 5, lane = gt & 31;
    if (n >= Nn) return;
    int g = batch[n];
    const float* hr = d_h + (size_t)n * 256;
#pragma unroll
    for (int q = lane; q < 64; q += 32) {
        float4 v = *(const float4*)(hr + (q << 2));
        atomicAdd(&d_pool[g * 256 + (q << 2) + 0], v.x);
        atomicAdd(&d_pool[g * 256 + (q << 2) + 1], v.y);
        atomicAdd(&d_pool[g * 256 + (q << 2) + 2], v.z);
        atomicAdd(&d_pool[g * 256 + (q << 2) + 3], v.w);
    }
    if (lane == 0) atomicAdd(&d_poolcnt[g], 1.0f);
}

__global__ void mlp_k(const float* __restrict__ meta,
                      const float* __restrict__ l1w, const float* __restrict__ l1b,
                      const float* __restrict__ l2w, const float* __restrict__ l2b,
                      float* __restrict__ out) {
    int g = blockIdx.x;
    int t = threadIdx.x;  // 128
    __shared__ float feat[294];
    __shared__ float red[128];
    float icnt = 1.0f / fmaxf(d_poolcnt[g], 1.0f);
    for (int c = t; c < 294; c += 128)
        feat[c] = (c < 256) ? d_pool[g * 256 + c] * icnt : meta[g * 38 + (c - 256)];
    __syncthreads();
    float val = 0.f;
    if (t < 100) {
        float a = l1b[t];
        for (int i = 0; i < 294; i++) a += feat[i] * l1w[i * 100 + t];
        val = a * l2w[t];
    }
    red[t] = val;
    __syncthreads();
    for (int s = 64; s > 0; s >>= 1) {
        if (t < s) red[t] += red[t + s];
        __syncthreads();
    }
    if (t == 0) out[g] = red[0] + l2b[0];
}

// ---------------- host launcher (graph-capturable, alloc-free) ----------------
extern "C" void kernel_launch(void* const* d_in, const int* in_sizes, int n_in,
                              void* d_out, int out_size) {
    const float* x    = (const float*)d_in[0];
    const int*   eidx = (const int*)d_in[2];
    const int*   srcp = eidx;
    const int*   dstp = eidx + Ee;
    const int*   et   = (const int*)d_in[3];
    const float* meta = (const float*)d_in[4];
    const int*   bat  = (const int*)d_in[5];

    // CSR build (structure-only, once per call)
    zero_ptr_k<<<(SEGS + 1 + 255) / 256, 256>>>();
    count_k<<<(Ee + 255) / 256, 256>>>(et, dstp);
    scan1_k<<<SCAN_BLKS, 256>>>();
    scan2_k<<<1, 256>>>();
    scan3_k<<<SCAN_BLKS, 256>>>();
    cursor_k<<<(SEGS + 255) / 256, 256>>>();
    fillcol_k<<<(Ee + 255) / 256, 256>>>(srcp, dstp, et);

    copy_x_k<<<(Nn * 128 / 4 + 255) / 256, 256>>>(x);

    const int dins[4]  = {128, 100, 256, 256};
    const int douts[4] = {100, 256, 256, 256};

    for (int l = 0; l < 4; l++) {
        int din = dins[l], dout = douts[l], K = 4 * din;
        int NB = (dout <= 128) ? 128 : 256;
        const float* W   = (const float*)d_in[6 + 5 * l];
        const float* Rw  = (const float*)d_in[7 + 5 * l];
        const float* bia = (const float*)d_in[8 + 5 * l];
        const float* gam = (const float*)d_in[9 + 5 * l];
        const float* bet = (const float*)d_in[10 + 5 * l];

        fillh_k<<<(Nn * (din / 4) + 255) / 256, 256>>>(din, K);
        gather_k<<<(SEGS * 32 + 255) / 256, 256>>>(din, K);
        prepB_k<<<(NB * (K / 2) + 255) / 256, 256>>>(W, Rw, K, din, dout, NB);
        mma_gemm_k<<<dim3((Nn + 127) / 128, NB / 128), 256>>>(bia, K, dout);
        zero_stat_k<<<1, 512>>>();
        stats_k<<<512, 256>>>(dout);
        prep_bn_k<<<1, 256>>>(gam, bet, dout);
        norm_k<<<((Nn * dout) / 4 + 255) / 256, 256>>>(dout);
    }

    zero_pool_k<<<(Gg * 256 + 255) / 256, 256>>>();
    pool_k<<<(Nn * 32 + 255) / 256, 256>>>(bat);
    mlp_k<<<Gg, 128>>>(meta, (const float*)d_in[26], (const float*)d_in[27],
                       (const float*)d_in[28], (const float*)d_in[29], (float*)d_out);
}